// round 4
// baseline (speedup 1.0000x reference)
#include <cuda_runtime.h>
#include <math.h>

// Problem constants
#define TLEN   2048
#define FDIM   256
#define NHEAD  8
#define NBATCH 4
#define NBH    32   // NBATCH * NHEAD

// GEMM tiling
constexpr int BM = 128, BN = 128, BK = 16;

// Scratch (allocation-free rule: __device__ globals)
__device__ float g_Q   [(size_t)NBH * TLEN * FDIM];            // 64 MB
__device__ float g_Kb  [(size_t)NBH * TLEN * FDIM];            // 64 MB
__device__ float g_V   [(size_t)NBH * TLEN * FDIM];            // 64 MB
__device__ float g_S   [(size_t)NBH * TLEN * TLEN];            // 512 MB
__device__ float g_attn[(size_t)NBATCH * TLEN * NHEAD * FDIM]; // 64 MB

// MODE 0: QKV   C[8192,6144] = x @ W_qkv + b, scatter -> Q/K/V [B,H,T,F], scale Q,K by 1/16
// MODE 1: SCORE C[2048,2048] = Q_bh @ K_bh^T (NT), z = b*H+h, store to g_S
// MODE 2: PV    C[2048, 256] = S_bh @ V_bh (NN), store to g_attn [B,T,H*F]
// MODE 3: PROJ  C[8192, 256] = attn @ W_proj + b_proj -> d_out
template<int MODE>
__global__ void __launch_bounds__(256)
gemm_kernel(const float* __restrict__ Agp, const float* __restrict__ Bgp,
            const float* __restrict__ bias, float* __restrict__ Cgp,
            int M, int N, int K)
{
    __shared__ float As[BK][BM + 4];
    __shared__ float Bs[BK][BN + 4];

    const int tid = threadIdx.x;
    const int tx = tid & 15, ty = tid >> 4;
    const int z  = blockIdx.z;
    const int rowBase = blockIdx.y * BM;
    const int colBase = blockIdx.x * BN;

    const float* __restrict__ A;
    const float* __restrict__ B;
    if      (MODE == 0) { A = Agp;                              B = Bgp; }
    else if (MODE == 1) { A = g_Q  + (size_t)z * TLEN * FDIM;   B = g_Kb + (size_t)z * TLEN * FDIM; }
    else if (MODE == 2) { A = g_S  + (size_t)z * TLEN * TLEN;   B = g_V  + (size_t)z * TLEN * FDIM; }
    else                { A = g_attn;                           B = Bgp; }

    constexpr bool TRANSB = (MODE == 1);

    // A tile: BM x BK (128x16) = 512 float4; each thread loads 2
    const int ar0 = tid >> 2;          // 0..63
    const int ar1 = (tid + 256) >> 2;  // 64..127
    const int akc = (tid & 3) << 2;    // 0,4,8,12
    // B tile NN: BK x BN (16x128)
    const int bnr0 = tid >> 5;            // 0..7
    const int bnr1 = (tid + 256) >> 5;    // 8..15
    const int bnc  = (tid & 31) << 2;     // 0..124

    const float* Arow = A + (size_t)rowBase * K;

    float4 a0, a1, b0, b1;

    // --- prologue: load tile kt=0 ---
    {
        a0 = *(const float4*)(Arow + (size_t)ar0 * K + akc);
        a1 = *(const float4*)(Arow + (size_t)ar1 * K + akc);
        if (TRANSB) {
            const float* Bp = B + (size_t)colBase * K;
            b0 = *(const float4*)(Bp + (size_t)ar0 * K + akc);
            b1 = *(const float4*)(Bp + (size_t)ar1 * K + akc);
        } else {
            const float* Bp = B + colBase;
            b0 = *(const float4*)(Bp + (size_t)bnr0 * N + bnc);
            b1 = *(const float4*)(Bp + (size_t)bnr1 * N + bnc);
        }
    }
    // store to smem
    {
        As[akc + 0][ar0] = a0.x; As[akc + 1][ar0] = a0.y; As[akc + 2][ar0] = a0.z; As[akc + 3][ar0] = a0.w;
        As[akc + 0][ar1] = a1.x; As[akc + 1][ar1] = a1.y; As[akc + 2][ar1] = a1.z; As[akc + 3][ar1] = a1.w;
        if (TRANSB) {
            Bs[akc + 0][ar0] = b0.x; Bs[akc + 1][ar0] = b0.y; Bs[akc + 2][ar0] = b0.z; Bs[akc + 3][ar0] = b0.w;
            Bs[akc + 0][ar1] = b1.x; Bs[akc + 1][ar1] = b1.y; Bs[akc + 2][ar1] = b1.z; Bs[akc + 3][ar1] = b1.w;
        } else {
            *(float4*)&Bs[bnr0][bnc] = b0;
            *(float4*)&Bs[bnr1][bnc] = b1;
        }
    }
    __syncthreads();

    float acc[8][8] = {};
    const int KT = K / BK;

    for (int kt = 0; kt < KT; ++kt) {
        // prefetch next tile global -> regs
        if (kt + 1 < KT) {
            const int k0 = (kt + 1) * BK;
            a0 = *(const float4*)(Arow + (size_t)ar0 * K + k0 + akc);
            a1 = *(const float4*)(Arow + (size_t)ar1 * K + k0 + akc);
            if (TRANSB) {
                const float* Bp = B + (size_t)colBase * K + k0;
                b0 = *(const float4*)(Bp + (size_t)ar0 * K + akc);
                b1 = *(const float4*)(Bp + (size_t)ar1 * K + akc);
            } else {
                const float* Bp = B + colBase + (size_t)k0 * N;
                b0 = *(const float4*)(Bp + (size_t)bnr0 * N + bnc);
                b1 = *(const float4*)(Bp + (size_t)bnr1 * N + bnc);
            }
        }

        #pragma unroll
        for (int k = 0; k < BK; ++k) {
            float4 x0 = *(const float4*)&As[k][ty * 8];
            float4 x1 = *(const float4*)&As[k][ty * 8 + 4];
            float4 y0 = *(const float4*)&Bs[k][tx * 8];
            float4 y1 = *(const float4*)&Bs[k][tx * 8 + 4];
            float ra[8] = {x0.x, x0.y, x0.z, x0.w, x1.x, x1.y, x1.z, x1.w};
            float rb[8] = {y0.x, y0.y, y0.z, y0.w, y1.x, y1.y, y1.z, y1.w};
            #pragma unroll
            for (int i = 0; i < 8; ++i)
                #pragma unroll
                for (int j = 0; j < 8; ++j)
                    acc[i][j] = fmaf(ra[i], rb[j], acc[i][j]);
        }
        __syncthreads();

        if (kt + 1 < KT) {
            As[akc + 0][ar0] = a0.x; As[akc + 1][ar0] = a0.y; As[akc + 2][ar0] = a0.z; As[akc + 3][ar0] = a0.w;
            As[akc + 0][ar1] = a1.x; As[akc + 1][ar1] = a1.y; As[akc + 2][ar1] = a1.z; As[akc + 3][ar1] = a1.w;
            if (TRANSB) {
                Bs[akc + 0][ar0] = b0.x; Bs[akc + 1][ar0] = b0.y; Bs[akc + 2][ar0] = b0.z; Bs[akc + 3][ar0] = b0.w;
                Bs[akc + 0][ar1] = b1.x; Bs[akc + 1][ar1] = b1.y; Bs[akc + 2][ar1] = b1.z; Bs[akc + 3][ar1] = b1.w;
            } else {
                *(float4*)&Bs[bnr0][bnc] = b0;
                *(float4*)&Bs[bnr1][bnc] = b1;
            }
            __syncthreads();
        }
    }

    // --- epilogue ---
    const int r0 = rowBase + ty * 8;
    const int c0 = colBase + tx * 8;

    if (MODE == 0) {
        #pragma unroll
        for (int i = 0; i < 8; ++i) {
            const int bt = r0 + i;
            const int b = bt >> 11;       // / TLEN
            const int t = bt & (TLEN - 1);
            #pragma unroll
            for (int j = 0; j < 8; ++j) {
                const int jj = c0 + j;
                float v = acc[i][j] + bias[jj];
                const int h = jj / (FDIM * 3);
                const int r = jj - h * (FDIM * 3);
                const int f = r / 3;
                const int c = r - f * 3;
                const size_t idx = (((size_t)(b * NHEAD + h)) * TLEN + t) * FDIM + f;
                if      (c == 0) g_Q [idx] = v * 0.0625f;  // 1/sqrt(256)
                else if (c == 1) g_Kb[idx] = v * 0.0625f;
                else             g_V [idx] = v;
            }
        }
    } else if (MODE == 1) {
        float* C = g_S + (size_t)z * TLEN * TLEN;
        #pragma unroll
        for (int i = 0; i < 8; ++i) {
            float* p = C + (size_t)(r0 + i) * TLEN + c0;
            *(float4*)(p)     = make_float4(acc[i][0], acc[i][1], acc[i][2], acc[i][3]);
            *(float4*)(p + 4) = make_float4(acc[i][4], acc[i][5], acc[i][6], acc[i][7]);
        }
    } else if (MODE == 2) {
        const int b = z >> 3, h = z & 7;
        #pragma unroll
        for (int i = 0; i < 8; ++i) {
            float* p = g_attn + ((size_t)(b * TLEN + r0 + i)) * (NHEAD * FDIM) + h * FDIM + c0;
            *(float4*)(p)     = make_float4(acc[i][0], acc[i][1], acc[i][2], acc[i][3]);
            *(float4*)(p + 4) = make_float4(acc[i][4], acc[i][5], acc[i][6], acc[i][7]);
        }
    } else {
        const float4 bv0 = *(const float4*)(bias + c0);
        const float4 bv1 = *(const float4*)(bias + c0 + 4);
        #pragma unroll
        for (int i = 0; i < 8; ++i) {
            float* p = Cgp + (size_t)(r0 + i) * N + c0;
            *(float4*)(p)     = make_float4(acc[i][0] + bv0.x, acc[i][1] + bv0.y,
                                            acc[i][2] + bv0.z, acc[i][3] + bv0.w);
            *(float4*)(p + 4) = make_float4(acc[i][4] + bv1.x, acc[i][5] + bv1.y,
                                            acc[i][6] + bv1.z, acc[i][7] + bv1.w);
        }
    }
}

// Row softmax over g_S: 65536 rows of 2048
__global__ void __launch_bounds__(256) softmax_kernel()
{
    const size_t row = blockIdx.x;
    float* p = g_S + row * (size_t)TLEN;
    const int t = threadIdx.x;

    float4 v0 = ((float4*)p)[t];
    float4 v1 = ((float4*)p)[t + 256];

    float m = fmaxf(fmaxf(fmaxf(v0.x, v0.y), fmaxf(v0.z, v0.w)),
                    fmaxf(fmaxf(v1.x, v1.y), fmaxf(v1.z, v1.w)));
    #pragma unroll
    for (int o = 16; o; o >>= 1) m = fmaxf(m, __shfl_xor_sync(0xffffffffu, m, o));

    __shared__ float red[8];
    const int warp = t >> 5, lane = t & 31;
    if (lane == 0) red[warp] = m;
    __syncthreads();
    float bm = red[0];
    #pragma unroll
    for (int i = 1; i < 8; ++i) bm = fmaxf(bm, red[i]);
    __syncthreads();

    v0.x = __expf(v0.x - bm); v0.y = __expf(v0.y - bm);
    v0.z = __expf(v0.z - bm); v0.w = __expf(v0.w - bm);
    v1.x = __expf(v1.x - bm); v1.y = __expf(v1.y - bm);
    v1.z = __expf(v1.z - bm); v1.w = __expf(v1.w - bm);

    float s = v0.x + v0.y + v0.z + v0.w + v1.x + v1.y + v1.z + v1.w;
    #pragma unroll
    for (int o = 16; o; o >>= 1) s += __shfl_xor_sync(0xffffffffu, s, o);
    if (lane == 0) red[warp] = s;
    __syncthreads();
    float bs = 0.f;
    #pragma unroll
    for (int i = 0; i < 8; ++i) bs += red[i];

    const float inv = 1.0f / bs;
    v0.x *= inv; v0.y *= inv; v0.z *= inv; v0.w *= inv;
    v1.x *= inv; v1.y *= inv; v1.z *= inv; v1.w *= inv;

    ((float4*)p)[t]       = v0;
    ((float4*)p)[t + 256] = v1;
}

extern "C" void kernel_launch(void* const* d_in, const int* in_sizes, int n_in,
                              void* d_out, int out_size)
{
    const float* x     = (const float*)d_in[0];
    const float* Wqkv  = (const float*)d_in[1];
    const float* bqkv  = (const float*)d_in[2];
    const float* Wproj = (const float*)d_in[3];
    const float* bproj = (const float*)d_in[4];
    float* out = (float*)d_out;

    const int Mx = NBATCH * TLEN;          // 8192
    const int Nqkv = NHEAD * FDIM * 3;     // 6144

    // 1) QKV GEMM + scatter
    gemm_kernel<0><<<dim3(Nqkv / BN, Mx / BM, 1), 256>>>(x, Wqkv, bqkv, nullptr,
                                                         Mx, Nqkv, FDIM);
    // 2) scores = Q K^T (batched over 32 bh)
    gemm_kernel<1><<<dim3(TLEN / BN, TLEN / BM, NBH), 256>>>(nullptr, nullptr, nullptr, nullptr,
                                                             TLEN, TLEN, FDIM);
    // 3) softmax rows
    softmax_kernel<<<NBH * TLEN, 256>>>();
    // 4) out_bh = P V  (batched), scatter into [B,T,H*F]
    gemm_kernel<2><<<dim3(FDIM / BN, TLEN / BM, NBH), 256>>>(nullptr, nullptr, nullptr, nullptr,
                                                             TLEN, FDIM, TLEN);
    // 5) proj
    gemm_kernel<3><<<dim3(FDIM / BN, Mx / BM, 1), 256>>>(nullptr, Wproj, bproj, out,
                                                         Mx, FDIM, TLEN);
}

// round 7
// speedup vs baseline: 2.3974x; 2.3974x over previous
#include <cuda_runtime.h>
#include <cstdint>
#include <math.h>

#define TLEN   2048
#define FDIM   256
#define NHEAD  8
#define NBATCH 4
#define NBH    32

// ---------------- scratch (__device__ globals; no allocation allowed) ----------------
__device__ float g_Q   [(size_t)NBH * TLEN * FDIM];            // [bh][t][f]
__device__ float g_Kb  [(size_t)NBH * TLEN * FDIM];            // [bh][t][f]
__device__ float g_Vt  [(size_t)NBH * FDIM * TLEN];            // [bh][f][t]
__device__ float g_S   [(size_t)NBH * TLEN * TLEN];            // scores / probs
__device__ float g_attn[(size_t)NBATCH * TLEN * NHEAD * FDIM]; // [b][t][h*f]
__device__ float g_WqkvT[(size_t)(NHEAD * FDIM * 3) * FDIM];   // [6144][256]
__device__ float g_WprojT[(size_t)FDIM * (NHEAD * FDIM)];      // [256][2048]

// ---------------- helpers ----------------
__device__ __forceinline__ uint32_t smem_u32(const void* p) {
    uint32_t a;
    asm("{ .reg .u64 t; cvta.to.shared.u64 t, %1; cvt.u32.u64 %0, t; }" : "=r"(a) : "l"(p));
    return a;
}
__device__ __forceinline__ void cp_async16(uint32_t dst, const void* src) {
    asm volatile("cp.async.cg.shared.global [%0], [%1], 16;" :: "r"(dst), "l"(src) : "memory");
}
__device__ __forceinline__ void cp_commit() {
    asm volatile("cp.async.commit_group;" ::: "memory");
}
template<int N> __device__ __forceinline__ void cp_wait() {
    asm volatile("cp.async.wait_group %0;" :: "n"(N) : "memory");
}
// m16n8k16 BF16 MMA (sm_80+, no arch-feature suffix -> compiles under compute_103)
__device__ __forceinline__ void mma_bf16(float* c, const uint32_t* a, const uint32_t* b) {
    asm volatile(
        "mma.sync.aligned.m16n8k16.row.col.f32.bf16.bf16.f32 "
        "{%0,%1,%2,%3}, {%4,%5,%6,%7}, {%8,%9}, {%0,%1,%2,%3};"
        : "+f"(c[0]), "+f"(c[1]), "+f"(c[2]), "+f"(c[3])
        : "r"(a[0]), "r"(a[1]), "r"(a[2]), "r"(a[3]), "r"(b[0]), "r"(b[1]));
}
// split fp32 pair -> packed bf16x2 hi + bf16x2 lo residual (lane order: .x = low half)
__device__ __forceinline__ void split_bf16(float2 f, uint32_t& hi, uint32_t& lo) {
    uint32_t h;
    asm("cvt.rn.bf16x2.f32 %0, %1, %2;" : "=r"(h) : "f"(f.y), "f"(f.x));
    const float h0 = __uint_as_float(h << 16);
    const float h1 = __uint_as_float(h & 0xffff0000u);
    const float l0 = f.x - h0;
    const float l1 = f.y - h1;
    asm("cvt.rn.bf16x2.f32 %0, %1, %2;" : "=r"(lo) : "f"(l1), "f"(l0));
    hi = h;
}

// ---------------- GEMM config ----------------
constexpr int BM = 128, BN = 128, BK = 32;
constexpr int SROW = BK + 8;                       // 40 words: 40 % 32 == 8 -> conflict-free 64b frag loads
constexpr int A_FLOATS = BM * SROW;                // 5120
constexpr int STAGE_FLOATS = 2 * A_FLOATS;         // A + B
constexpr int STAGE_BYTES  = STAGE_FLOATS * 4;     // 40960
constexpr int SMEM_NEED    = 2 * STAGE_BYTES;      // 81920 (2 stages)

// MODE 0: C[8192,6144] = x @ WqkvT^T   (K=256)  -> scatter Q/K/Vt (+bias, *1/16)
// MODE 1: C[2048,2048] = Q_bh @ K_bh^T (K=256)  -> g_S
// MODE 2: C[2048, 256] = S_bh @ Vt_bh^T(K=2048) -> g_attn [B,T,H*F]
// MODE 3: C[8192, 256] = attn @ WprojT^T (K=2048) -> d_out (+bias)
template<int MODE>
__global__ void __launch_bounds__(256, 2)
mma_gemm(const float* __restrict__ Agp, const float* __restrict__ bias, float* __restrict__ Cgp)
{
    constexpr int K  = (MODE == 0 || MODE == 1) ? 256 : 2048;
    constexpr int KT = K / BK;

    extern __shared__ float smem_f[];
    const uint32_t sbase = smem_u32(smem_f);

    const int tid = threadIdx.x;
    const int wid = tid >> 5, lid = tid & 31;
    const int z = blockIdx.z;
    const int rowBase = blockIdx.y * BM;
    const int colBase = blockIdx.x * BN;

    const float* A;
    const float* B;
    if      (MODE == 0) { A = Agp;                               B = g_WqkvT; }
    else if (MODE == 1) { A = g_Q  + (size_t)z * TLEN * FDIM;    B = g_Kb + (size_t)z * TLEN * FDIM; }
    else if (MODE == 2) { A = g_S  + (size_t)z * TLEN * TLEN;    B = g_Vt + (size_t)z * FDIM * TLEN; }
    else                { A = g_attn;                            B = g_WprojT; }

    const float* Asrc = A + (size_t)rowBase * K;
    const float* Bsrc = B + (size_t)colBase * K;

    // loader mapping: 1024 16B-chunks per tile per matrix; 4 per thread
    auto load_tile = [&](int kt, int s) {
        const uint32_t base = sbase + s * STAGE_BYTES;
        const size_t kofs = (size_t)kt * BK;
        #pragma unroll
        for (int i = 0; i < 4; ++i) {
            const int f   = tid + 256 * i;
            const int row = f >> 3;
            const int c4  = (f & 7) << 2;
            const uint32_t so = (uint32_t)(row * SROW + c4) * 4;
            cp_async16(base + so,                  Asrc + (size_t)row * K + kofs + c4);
            cp_async16(base + A_FLOATS * 4 + so,   Bsrc + (size_t)row * K + kofs + c4);
        }
        cp_commit();
    };

    const int warp_m = wid & 3;   // 4 warps along M -> 32 rows each
    const int warp_n = wid >> 2;  // 2 warps along N -> 64 cols each
    const int gid = lid >> 2;     // 0..7
    const int tig = lid & 3;      // 0..3

    float acc[2][8][4];
    #pragma unroll
    for (int i = 0; i < 2; ++i)
        #pragma unroll
        for (int j = 0; j < 8; ++j)
            #pragma unroll
            for (int c = 0; c < 4; ++c) acc[i][j][c] = 0.f;

    load_tile(0, 0);

    #pragma unroll 1
    for (int kt = 0; kt < KT; ++kt) {
        const int s = kt & 1;
        if (kt + 1 < KT) { load_tile(kt + 1, s ^ 1); cp_wait<1>(); }
        else             { cp_wait<0>(); }
        __syncthreads();

        const float* As = smem_f + s * STAGE_FLOATS + (32 * warp_m) * SROW;
        const float* Bs = smem_f + s * STAGE_FLOATS + A_FLOATS + (64 * warp_n) * SROW;

        #pragma unroll
        for (int ks = 0; ks < 2; ++ks) {          // two m16n8k16 K-steps per BK=32
            const int k0 = ks * 16 + 2 * tig;

            // A fragments (hi/lo) for both 16-row blocks
            uint32_t ah[2][4], al[2][4];
            #pragma unroll
            for (int i = 0; i < 2; ++i) {
                const float* p = As + (16 * i + gid) * SROW + k0;
                split_bf16(*(const float2*)(p),                ah[i][0], al[i][0]);
                split_bf16(*(const float2*)(p + 8 * SROW),     ah[i][1], al[i][1]);
                split_bf16(*(const float2*)(p + 8),            ah[i][2], al[i][2]);
                split_bf16(*(const float2*)(p + 8 * SROW + 8), ah[i][3], al[i][3]);
            }

            // B fragments in two halves of 4 columns (register pressure)
            #pragma unroll
            for (int jh = 0; jh < 2; ++jh) {
                uint32_t bh[4][2], bl[4][2];
                #pragma unroll
                for (int j = 0; j < 4; ++j) {
                    const float* p = Bs + (8 * (jh * 4 + j) + gid) * SROW + k0;
                    split_bf16(*(const float2*)(p),     bh[j][0], bl[j][0]);
                    split_bf16(*(const float2*)(p + 8), bh[j][1], bl[j][1]);
                }
                #pragma unroll
                for (int i = 0; i < 2; ++i)
                    #pragma unroll
                    for (int j = 0; j < 4; ++j) {
                        float* c = acc[i][jh * 4 + j];
                        mma_bf16(c, ah[i], bh[j]);   // hi*hi
                        mma_bf16(c, ah[i], bl[j]);   // hi*lo
                        mma_bf16(c, al[i], bh[j]);   // lo*hi
                    }
            }
        }
        __syncthreads();
    }

    // ---------------- epilogue ----------------
    const int gm = rowBase + 32 * warp_m;
    const int gn = colBase + 64 * warp_n + 2 * tig;

    #pragma unroll
    for (int i = 0; i < 2; ++i) {
        #pragma unroll
        for (int h = 0; h < 2; ++h) {
            const int m = gm + 16 * i + gid + 8 * h;

            if (MODE == 0) {
                const int b = m >> 11, t = m & (TLEN - 1);
                #pragma unroll
                for (int j = 0; j < 8; ++j) {
                    #pragma unroll
                    for (int c = 0; c < 2; ++c) {
                        const int jj = gn + 8 * j + c;
                        const float v = acc[i][j][2 * h + c] + bias[jj];
                        const int hh = jj / (FDIM * 3);
                        const int rr = jj - hh * (FDIM * 3);
                        const int f  = rr / 3;
                        const int cc = rr - f * 3;
                        const size_t bh = (size_t)(b * NHEAD + hh);
                        if      (cc == 0) g_Q [(bh * TLEN + t) * FDIM + f] = v * 0.0625f;
                        else if (cc == 1) g_Kb[(bh * TLEN + t) * FDIM + f] = v * 0.0625f;
                        else              g_Vt[(bh * FDIM + f) * TLEN + t] = v;
                    }
                }
            } else if (MODE == 1) {
                float* p = g_S + (size_t)z * TLEN * TLEN + (size_t)m * TLEN + gn;
                #pragma unroll
                for (int j = 0; j < 8; ++j)
                    *(float2*)(p + 8 * j) = make_float2(acc[i][j][2 * h], acc[i][j][2 * h + 1]);
            } else if (MODE == 2) {
                const int b = z >> 3, hh = z & 7;
                float* p = g_attn + ((size_t)(b * TLEN + m)) * (NHEAD * FDIM) + hh * FDIM + gn;
                #pragma unroll
                for (int j = 0; j < 8; ++j)
                    *(float2*)(p + 8 * j) = make_float2(acc[i][j][2 * h], acc[i][j][2 * h + 1]);
            } else {
                float* p = Cgp + (size_t)m * FDIM + gn;
                #pragma unroll
                for (int j = 0; j < 8; ++j)
                    *(float2*)(p + 8 * j) = make_float2(acc[i][j][2 * h]     + bias[gn + 8 * j],
                                                        acc[i][j][2 * h + 1] + bias[gn + 8 * j + 1]);
            }
        }
    }
}

// ---------------- weight transposes ----------------
template<int W>
__global__ void __launch_bounds__(256) transpose_kernel(const float* __restrict__ in)
{
    constexpr int R = (W == 0) ? FDIM : (NHEAD * FDIM);   // input rows
    constexpr int C = (W == 0) ? (NHEAD * FDIM * 3) : FDIM;
    float* out = (W == 0) ? g_WqkvT : g_WprojT;           // [C][R]

    __shared__ float t[32][33];
    const int cx = blockIdx.x * 32 + threadIdx.x;
    const int ry = blockIdx.y * 32 + threadIdx.y;
    #pragma unroll
    for (int i = 0; i < 32; i += 8)
        t[threadIdx.y + i][threadIdx.x] = in[(size_t)(ry + i) * C + cx];
    __syncthreads();
    const int oc = blockIdx.y * 32 + threadIdx.x;
    const int orow = blockIdx.x * 32 + threadIdx.y;
    #pragma unroll
    for (int i = 0; i < 32; i += 8)
        out[(size_t)(orow + i) * R + oc] = t[threadIdx.x][threadIdx.y + i];
}

// ---------------- softmax: 65536 rows of 2048 ----------------
__global__ void __launch_bounds__(256) softmax_kernel()
{
    const size_t row = blockIdx.x;
    float* p = g_S + row * (size_t)TLEN;
    const int t = threadIdx.x;

    float4 v0 = ((float4*)p)[t];
    float4 v1 = ((float4*)p)[t + 256];

    float m = fmaxf(fmaxf(fmaxf(v0.x, v0.y), fmaxf(v0.z, v0.w)),
                    fmaxf(fmaxf(v1.x, v1.y), fmaxf(v1.z, v1.w)));
    #pragma unroll
    for (int o = 16; o; o >>= 1) m = fmaxf(m, __shfl_xor_sync(0xffffffffu, m, o));

    __shared__ float red[8];
    const int warp = t >> 5, lane = t & 31;
    if (lane == 0) red[warp] = m;
    __syncthreads();
    float bm = red[0];
    #pragma unroll
    for (int i = 1; i < 8; ++i) bm = fmaxf(bm, red[i]);
    __syncthreads();

    v0.x = __expf(v0.x - bm); v0.y = __expf(v0.y - bm);
    v0.z = __expf(v0.z - bm); v0.w = __expf(v0.w - bm);
    v1.x = __expf(v1.x - bm); v1.y = __expf(v1.y - bm);
    v1.z = __expf(v1.z - bm); v1.w = __expf(v1.w - bm);

    float s = v0.x + v0.y + v0.z + v0.w + v1.x + v1.y + v1.z + v1.w;
    #pragma unroll
    for (int o = 16; o; o >>= 1) s += __shfl_xor_sync(0xffffffffu, s, o);
    if (lane == 0) red[warp] = s;
    __syncthreads();
    float bs = 0.f;
    #pragma unroll
    for (int i = 0; i < 8; ++i) bs += red[i];

    const float inv = 1.0f / bs;
    v0.x *= inv; v0.y *= inv; v0.z *= inv; v0.w *= inv;
    v1.x *= inv; v1.y *= inv; v1.z *= inv; v1.w *= inv;

    ((float4*)p)[t]       = v0;
    ((float4*)p)[t + 256] = v1;
}

// ---------------- launch ----------------
extern "C" void kernel_launch(void* const* d_in, const int* in_sizes, int n_in,
                              void* d_out, int out_size)
{
    const float* x     = (const float*)d_in[0];
    const float* Wqkv  = (const float*)d_in[1];
    const float* bqkv  = (const float*)d_in[2];
    const float* Wproj = (const float*)d_in[3];
    const float* bproj = (const float*)d_in[4];
    float* out = (float*)d_out;

    cudaFuncSetAttribute(mma_gemm<0>, cudaFuncAttributeMaxDynamicSharedMemorySize, SMEM_NEED);
    cudaFuncSetAttribute(mma_gemm<1>, cudaFuncAttributeMaxDynamicSharedMemorySize, SMEM_NEED);
    cudaFuncSetAttribute(mma_gemm<2>, cudaFuncAttributeMaxDynamicSharedMemorySize, SMEM_NEED);
    cudaFuncSetAttribute(mma_gemm<3>, cudaFuncAttributeMaxDynamicSharedMemorySize, SMEM_NEED);

    // weight transposes (W_qkv: [256,6144] -> [6144,256]; W_proj: [2048,256] -> [256,2048])
    transpose_kernel<0><<<dim3(6144 / 32, 256 / 32), dim3(32, 8)>>>(Wqkv);
    transpose_kernel<1><<<dim3(256 / 32, 2048 / 32), dim3(32, 8)>>>(Wproj);

    // 1) QKV GEMM (+bias, scale, scatter to Q/K/Vt)
    mma_gemm<0><<<dim3(6144 / BN, 8192 / BM, 1), 256, SMEM_NEED>>>(x, bqkv, nullptr);
    // 2) scores = Q K^T (batched over 32 bh)
    mma_gemm<1><<<dim3(TLEN / BN, TLEN / BM, NBH), 256, SMEM_NEED>>>(nullptr, nullptr, nullptr);
    // 3) softmax
    softmax_kernel<<<NBH * TLEN, 256>>>();
    // 4) out = P V (batched, NT against Vt)
    mma_gemm<2><<<dim3(FDIM / BN, TLEN / BM, NBH), 256, SMEM_NEED>>>(nullptr, nullptr, nullptr);
    // 5) proj (+bias)
    mma_gemm<3><<<dim3(FDIM / BN, 8192 / BM, 1), 256, SMEM_NEED>>>(nullptr, bproj, out);
}